// round 1
// baseline (speedup 1.0000x reference)
#include <cuda_runtime.h>
#include <math.h>

#define T_ 16
#define B_ 1024
#define F_DIM 512
#define H_ 128
#define L_ 512
#define C_ 100
#define KSPLIT 8

// Scratch (static device globals -- no allocation allowed)
__device__ float g_h[(size_t)T_ * B_ * H_];          // 8 MB
__device__ float g_p[(size_t)T_ * B_ * L_];          // 32 MB
__device__ float g_mu[(size_t)T_ * B_ * L_];         // 32 MB
__device__ float g_leafp[(size_t)T_ * L_ * C_];      // 3.3 MB
__device__ float g_part[(size_t)KSPLIT * B_ * C_];   // 3.3 MB

// ---------------------------------------------------------------------------
// Fused GEMM + bias + activation.
// MODE 0: h = relu(feat @ W1 + b1)      A=feat (B_,512), W=(T,512,128), out=g_h
// MODE 1: p = sigmoid(h @ W2 + b2)      A=g_h  (T,B_,128), W=(T,128,512), out=g_p
// Block tile 128x128, BK=16, 256 threads, 8x8 microtile.
// ---------------------------------------------------------------------------
template <int MODE>
__global__ __launch_bounds__(256) void gemm_fused(const float* __restrict__ Aext,
                                                  const float* __restrict__ W,
                                                  const float* __restrict__ bias) {
    constexpr int KDIM = MODE ? H_ : F_DIM;
    constexpr int NTOT = MODE ? L_ : H_;

    __shared__ float As[128][17];   // padded: conflict-free a-frag reads
    __shared__ float Bs[16][128];

    const int t  = blockIdx.z;
    const int b0 = blockIdx.x * 128;
    const int n0 = blockIdx.y * 128;

    const float* Ab = (MODE == 0) ? Aext : (g_h + (size_t)t * B_ * KDIM);
    const float* Wb = W + (size_t)t * KDIM * NTOT + n0;
    const float* bb = bias + (size_t)t * NTOT + n0;
    float* ob = (MODE == 0 ? g_h : g_p) + (size_t)t * B_ * NTOT + (size_t)b0 * NTOT + n0;

    const int tid = threadIdx.x;
    const int tx = tid & 15;   // col group: cols tx*8 + j
    const int ty = tid >> 4;   // row group: rows ty*8 + i

    float acc[8][8];
#pragma unroll
    for (int i = 0; i < 8; i++)
#pragma unroll
        for (int j = 0; j < 8; j++) acc[i][j] = 0.0f;

    for (int k0 = 0; k0 < KDIM; k0 += 16) {
        // Load A tile 128x16 (float4, scatter into padded smem)
#pragma unroll
        for (int i = 0; i < 2; i++) {
            int e = tid + i * 256;        // 512 float4 slots
            int r = e >> 2, c4 = e & 3;
            float4 v = *reinterpret_cast<const float4*>(
                &Ab[(size_t)(b0 + r) * KDIM + k0 + c4 * 4]);
            As[r][c4 * 4 + 0] = v.x;
            As[r][c4 * 4 + 1] = v.y;
            As[r][c4 * 4 + 2] = v.z;
            As[r][c4 * 4 + 3] = v.w;
        }
        // Load B tile 16x128 (float4)
#pragma unroll
        for (int i = 0; i < 2; i++) {
            int e = tid + i * 256;
            int kk = e >> 5, n4 = e & 31;
            *reinterpret_cast<float4*>(&Bs[kk][n4 * 4]) =
                *reinterpret_cast<const float4*>(&Wb[(size_t)(k0 + kk) * NTOT + n4 * 4]);
        }
        __syncthreads();

#pragma unroll
        for (int k = 0; k < 16; k++) {
            float a[8], bv[8];
#pragma unroll
            for (int i = 0; i < 8; i++) a[i] = As[ty * 8 + i][k];
            float4 u0 = *reinterpret_cast<const float4*>(&Bs[k][tx * 8]);
            float4 u1 = *reinterpret_cast<const float4*>(&Bs[k][tx * 8 + 4]);
            bv[0] = u0.x; bv[1] = u0.y; bv[2] = u0.z; bv[3] = u0.w;
            bv[4] = u1.x; bv[5] = u1.y; bv[6] = u1.z; bv[7] = u1.w;
#pragma unroll
            for (int i = 0; i < 8; i++)
#pragma unroll
                for (int j = 0; j < 8; j++) acc[i][j] += a[i] * bv[j];
        }
        __syncthreads();
    }

    // Epilogue: bias + activation, vectorized stores
#pragma unroll
    for (int i = 0; i < 8; i++) {
        int r = ty * 8 + i;
        float res[8];
#pragma unroll
        for (int j = 0; j < 8; j++) {
            int c = tx * 8 + j;
            float x = acc[i][j] + bb[c];
            if (MODE == 0)
                res[j] = fmaxf(x, 0.0f);
            else
                res[j] = 1.0f / (1.0f + __expf(-x));
        }
        float4* op = reinterpret_cast<float4*>(&ob[(size_t)r * NTOT + tx * 8]);
        op[0] = make_float4(res[0], res[1], res[2], res[3]);
        op[1] = make_float4(res[4], res[5], res[6], res[7]);
    }
}

// ---------------------------------------------------------------------------
// Leaf softmax: leafp[t,l,:] = softmax(pi[t,l,:]). One warp per (t,l) row.
// ---------------------------------------------------------------------------
__global__ __launch_bounds__(128) void leaf_softmax_kernel(const float* __restrict__ pi) {
    const int row = blockIdx.x * 4 + (threadIdx.x >> 5);  // 0 .. T*L-1
    const int lane = threadIdx.x & 31;
    const float* pr = pi + (size_t)row * C_;

    float v[4];
#pragma unroll
    for (int j = 0; j < 4; j++) {
        int c = lane + j * 32;
        v[j] = (c < C_) ? pr[c] : -1e30f;
    }
    float m = fmaxf(fmaxf(v[0], v[1]), fmaxf(v[2], v[3]));
#pragma unroll
    for (int o = 16; o; o >>= 1) m = fmaxf(m, __shfl_xor_sync(0xffffffffu, m, o));

    float e[4];
    float s = 0.0f;
#pragma unroll
    for (int j = 0; j < 4; j++) {
        int c = lane + j * 32;
        e[j] = (c < C_) ? __expf(v[j] - m) : 0.0f;
        s += e[j];
    }
#pragma unroll
    for (int o = 16; o; o >>= 1) s += __shfl_xor_sync(0xffffffffu, s, o);
    float inv = 1.0f / s;
#pragma unroll
    for (int j = 0; j < 4; j++) {
        int c = lane + j * 32;
        if (c < C_) g_leafp[(size_t)row * C_ + c] = e[j] * inv;
    }
}

// ---------------------------------------------------------------------------
// mu[t,b,l] = prod_{d=0..8} route(p[t,b,node(d,l)], side(d,l))
// One block per (t,b) row; p row staged in shared.
// ---------------------------------------------------------------------------
__global__ __launch_bounds__(128) void mu_kernel() {
    __shared__ float sp[L_];
    const size_t tb = blockIdx.x;  // t*B + b
    const float* pr = g_p + tb * L_;
    const int tid = threadIdx.x;
#pragma unroll
    for (int i = 0; i < 4; i++) sp[tid + i * 128] = pr[tid + i * 128];
    __syncthreads();
#pragma unroll
    for (int i = 0; i < 4; i++) {
        int l = tid + i * 128;
        float prod = 1.0f;
#pragma unroll
        for (int d = 0; d <= 8; d++) {
            int node = (1 << d) - 1 + (l >> (9 - d));
            float v = sp[node];
            prod *= ((l >> (8 - d)) & 1) ? (1.0f - v) : v;
        }
        g_mu[tb * L_ + l] = prod;
    }
}

// ---------------------------------------------------------------------------
// Final contraction: part[ks, b, c] = sum over K-chunk of mu[t,b,l]*leafp[t,l,c]
// M=1024, N=100 (padded to 128), K=8192 split into KSPLIT chunks of 1024.
// Block tile 64x128, BK=32, 256 threads, 4x8 microtile.
// ---------------------------------------------------------------------------
__global__ __launch_bounds__(256) void final_gemm_kernel() {
    __shared__ float As[64][33];
    __shared__ float Bs[32][128];

    const int b0 = blockIdx.x * 64;
    const int ks = blockIdx.y;
    const int tid = threadIdx.x;
    const int tx = tid & 15;   // cols tx*8 + j
    const int ty = tid >> 4;   // rows ty*4 + i

    float acc[4][8];
#pragma unroll
    for (int i = 0; i < 4; i++)
#pragma unroll
        for (int j = 0; j < 8; j++) acc[i][j] = 0.0f;

    for (int kt = 0; kt < 32; kt++) {
        const int kg = ks * 1024 + kt * 32;  // global k, 32-aligned within one tree
        const int t = kg >> 9;
        const int l0 = kg & 511;

        const float* mb = g_mu + (size_t)t * B_ * L_ + (size_t)b0 * L_ + l0;
#pragma unroll
        for (int i = 0; i < 2; i++) {
            int e = tid + i * 256;   // 512 float4 slots (64x32)
            int r = e >> 3, c4 = e & 7;
            float4 v = *reinterpret_cast<const float4*>(&mb[(size_t)r * L_ + c4 * 4]);
            As[r][c4 * 4 + 0] = v.x;
            As[r][c4 * 4 + 1] = v.y;
            As[r][c4 * 4 + 2] = v.z;
            As[r][c4 * 4 + 3] = v.w;
        }
        const float* lb = g_leafp + ((size_t)t * L_ + l0) * C_;
#pragma unroll
        for (int i = 0; i < 16; i++) {
            int e = tid + i * 256;   // 4096 scalars (32x128)
            int kk = e >> 7, n = e & 127;
            Bs[kk][n] = (n < C_) ? lb[(size_t)kk * C_ + n] : 0.0f;
        }
        __syncthreads();

#pragma unroll
        for (int k = 0; k < 32; k++) {
            float a[4], bv[8];
#pragma unroll
            for (int i = 0; i < 4; i++) a[i] = As[ty * 4 + i][k];
            float4 u0 = *reinterpret_cast<const float4*>(&Bs[k][tx * 8]);
            float4 u1 = *reinterpret_cast<const float4*>(&Bs[k][tx * 8 + 4]);
            bv[0] = u0.x; bv[1] = u0.y; bv[2] = u0.z; bv[3] = u0.w;
            bv[4] = u1.x; bv[5] = u1.y; bv[6] = u1.z; bv[7] = u1.w;
#pragma unroll
            for (int i = 0; i < 4; i++)
#pragma unroll
                for (int j = 0; j < 8; j++) acc[i][j] += a[i] * bv[j];
        }
        __syncthreads();
    }

    float* pb = g_part + (size_t)ks * B_ * C_;
#pragma unroll
    for (int i = 0; i < 4; i++) {
        int b = b0 + ty * 4 + i;
#pragma unroll
        for (int j = 0; j < 8; j++) {
            int c = tx * 8 + j;
            if (c < C_) pb[(size_t)b * C_ + c] = acc[i][j];
        }
    }
}

// ---------------------------------------------------------------------------
// Deterministic reduction over k-splits + final log
// ---------------------------------------------------------------------------
__global__ __launch_bounds__(256) void reduce_log_kernel(float* __restrict__ out) {
    const int i = blockIdx.x * 256 + threadIdx.x;  // 0 .. B*C-1 (102400)
    float s = 0.0f;
#pragma unroll
    for (int ks = 0; ks < KSPLIT; ks++) s += g_part[(size_t)ks * B_ * C_ + i];
    out[i] = logf(s * (1.0f / (float)(L_ * T_)));
}

extern "C" void kernel_launch(void* const* d_in, const int* in_sizes, int n_in,
                              void* d_out, int out_size) {
    const float* feat = (const float*)d_in[0];
    const float* W1 = (const float*)d_in[1];
    const float* b1 = (const float*)d_in[2];
    const float* W2 = (const float*)d_in[3];
    const float* b2 = (const float*)d_in[4];
    const float* pi = (const float*)d_in[5];
    float* out = (float*)d_out;

    // Stage 1: h = relu(feat @ W1 + b1)         grid (B/128, 1, T)
    gemm_fused<0><<<dim3(B_ / 128, 1, T_), 256>>>(feat, W1, b1);
    // Stage 2: p = sigmoid(h @ W2 + b2)         grid (B/128, L/128, T)
    gemm_fused<1><<<dim3(B_ / 128, L_ / 128, T_), 256>>>(nullptr, W2, b2);
    // Leaf softmax (independent of stages 1-2)
    leaf_softmax_kernel<<<(T_ * L_) / 4, 128>>>(pi);
    // Routing products
    mu_kernel<<<T_ * B_, 128>>>();
    // Final contraction with deterministic K-split partials
    final_gemm_kernel<<<dim3(B_ / 64, KSPLIT), 256>>>();
    // Reduce + log
    reduce_log_kernel<<<(B_ * C_) / 256, 256>>>(out);
}

// round 2
// speedup vs baseline: 2.1554x; 2.1554x over previous
#include <cuda_runtime.h>
#include <math.h>

#define T_ 16
#define B_ 1024
#define F_DIM 512
#define H_ 128
#define L_ 512
#define C_ 100
#define KSPLIT 16

// Scratch (static device globals -- no allocation allowed)
__device__ float g_h[(size_t)T_ * B_ * H_];          // 8 MB
__device__ float g_p[(size_t)T_ * B_ * L_];          // 32 MB
__device__ float g_mu[(size_t)T_ * B_ * L_];         // 32 MB
__device__ float g_leafp[(size_t)T_ * L_ * C_];      // 3.3 MB
__device__ float g_part[(size_t)KSPLIT * B_ * C_];   // 6.5 MB

__device__ __forceinline__ unsigned f2tf32(float x) {
    unsigned r;
    asm("cvt.rna.tf32.f32 %0, %1;" : "=r"(r) : "f"(x));
    return r;
}

__device__ __forceinline__ void mma_tf32(float* d, const unsigned* a, const unsigned* b) {
    asm volatile(
        "mma.sync.aligned.m16n8k8.row.col.f32.tf32.tf32.f32 "
        "{%0,%1,%2,%3}, {%4,%5,%6,%7}, {%8,%9}, {%0,%1,%2,%3};\n"
        : "+f"(d[0]), "+f"(d[1]), "+f"(d[2]), "+f"(d[3])
        : "r"(a[0]), "r"(a[1]), "r"(a[2]), "r"(a[3]), "r"(b[0]), "r"(b[1]));
}

// ---------------------------------------------------------------------------
// tf32 tensor-core GEMM, 128x128 block tile, BK=32, 256 threads.
// MODE 0: h = relu(feat @ W1 + b1)        KDIM=512 NTOT=128
// MODE 1: p = sigmoid(h @ W2 + b2)        KDIM=128 NTOT=512
// MODE 2: part[t] = mu[t] @ leafp[t]      KDIM=512 NTOT=100 (N padded to 128)
// ---------------------------------------------------------------------------
template <int MODE, int KDIM, int NTOT>
__global__ __launch_bounds__(256) void gemm_tf32(const float* __restrict__ A,
                                                 const float* __restrict__ Bmat,
                                                 const float* __restrict__ bias) {
    __shared__ unsigned As[128][36];   // m-major, stride 36: bank (4m+k)%32 distinct
    __shared__ unsigned Bs[32][136];   // k-major, stride 136: bank (8k+n)%32 distinct

    const int tid = threadIdx.x;
    const int wid = tid >> 5, lane = tid & 31;
    const int warp_m = wid >> 2;         // 0..1 -> rows warp_m*64
    const int warp_n = wid & 3;          // 0..3 -> cols warp_n*32
    const int lq = lane >> 2;            // lane/4
    const int lr = lane & 3;             // lane%4
    const int b0 = blockIdx.x * 128;

    const float *Ab, *Bb, *bb = nullptr;
    float* ob;
    if (MODE == 0) {
        const int t = blockIdx.z;
        Ab = A;
        Bb = Bmat + (size_t)t * F_DIM * H_;
        bb = bias + (size_t)t * H_;
        ob = g_h + ((size_t)t * B_ + b0) * H_;
    } else if (MODE == 1) {
        const int t = blockIdx.z;
        const int n0 = blockIdx.y * 128;
        Ab = g_h + (size_t)t * B_ * H_;
        Bb = Bmat + (size_t)t * H_ * L_ + n0;
        bb = bias + (size_t)t * L_ + n0;
        ob = g_p + ((size_t)t * B_ + b0) * L_ + n0;
    } else {
        const int t = blockIdx.y;        // one tree per k-split
        Ab = g_mu + (size_t)t * B_ * L_;
        Bb = g_leafp + (size_t)t * L_ * C_;
        ob = g_part + ((size_t)t * B_ + b0) * C_;
    }

    float acc[4][4][4];
#pragma unroll
    for (int i = 0; i < 4; i++)
#pragma unroll
        for (int j = 0; j < 4; j++)
#pragma unroll
            for (int q = 0; q < 4; q++) acc[i][j][q] = 0.0f;

    for (int k0 = 0; k0 < KDIM; k0 += 32) {
        // A tile: 128 rows x 32 k (8 float4/row). 1024 float4 / 256 thr = 4 each.
#pragma unroll
        for (int i = 0; i < 4; i++) {
            int e = tid + i * 256;
            int r = e >> 3, c4 = e & 7;
            float4 v = *reinterpret_cast<const float4*>(&Ab[(size_t)(b0 + r) * KDIM + k0 + c4 * 4]);
            uint4 u;
            u.x = f2tf32(v.x); u.y = f2tf32(v.y); u.z = f2tf32(v.z); u.w = f2tf32(v.w);
            *reinterpret_cast<uint4*>(&As[r][c4 * 4]) = u;
        }
        // B tile: 32 k-rows x 128 n (zero-padded past C_ in MODE 2).
#pragma unroll
        for (int i = 0; i < 4; i++) {
            int e = tid + i * 256;
            int kk = e >> 5, n4 = e & 31;
            uint4 u;
            if (MODE == 2 && n4 >= C_ / 4) {
                u = make_uint4(0u, 0u, 0u, 0u);
            } else {
                float4 v = *reinterpret_cast<const float4*>(&Bb[(size_t)(k0 + kk) * NTOT + n4 * 4]);
                u.x = f2tf32(v.x); u.y = f2tf32(v.y); u.z = f2tf32(v.z); u.w = f2tf32(v.w);
            }
            *reinterpret_cast<uint4*>(&Bs[kk][n4 * 4]) = u;
        }
        __syncthreads();

#pragma unroll
        for (int k8 = 0; k8 < 4; k8++) {
            const int kb = k8 * 8;
            unsigned afr[4][4], bfr[4][2];
#pragma unroll
            for (int im = 0; im < 4; im++) {
                int r = warp_m * 64 + im * 16;
                afr[im][0] = As[r + lq][kb + lr];
                afr[im][1] = As[r + 8 + lq][kb + lr];
                afr[im][2] = As[r + lq][kb + 4 + lr];
                afr[im][3] = As[r + 8 + lq][kb + 4 + lr];
            }
#pragma unroll
            for (int jn = 0; jn < 4; jn++) {
                int c = warp_n * 32 + jn * 8 + lq;
                bfr[jn][0] = Bs[kb + lr][c];
                bfr[jn][1] = Bs[kb + 4 + lr][c];
            }
#pragma unroll
            for (int im = 0; im < 4; im++)
#pragma unroll
                for (int jn = 0; jn < 4; jn++) mma_tf32(acc[im][jn], afr[im], bfr[jn]);
        }
        __syncthreads();
    }

    // Epilogue. d-frag layout: rows lq (+8), cols lr*2 (+1) within each 16x8 tile.
#pragma unroll
    for (int im = 0; im < 4; im++) {
#pragma unroll
        for (int half = 0; half < 2; half++) {
            int r = warp_m * 64 + im * 16 + half * 8 + lq;
#pragma unroll
            for (int jn = 0; jn < 4; jn++) {
                int c = warp_n * 32 + jn * 8 + lr * 2;
                float x0 = acc[im][jn][half * 2 + 0];
                float x1 = acc[im][jn][half * 2 + 1];
                if (MODE == 0) {
                    x0 = fmaxf(x0 + bb[c], 0.0f);
                    x1 = fmaxf(x1 + bb[c + 1], 0.0f);
                } else if (MODE == 1) {
                    x0 = 1.0f / (1.0f + __expf(-(x0 + bb[c])));
                    x1 = 1.0f / (1.0f + __expf(-(x1 + bb[c + 1])));
                }
                if (MODE == 2 && c >= C_) continue;
                *reinterpret_cast<float2*>(&ob[(size_t)r * NTOT + c]) = make_float2(x0, x1);
            }
        }
    }
}

// ---------------------------------------------------------------------------
// Leaf softmax: leafp[t,l,:] = softmax(pi[t,l,:]). One warp per (t,l) row.
// ---------------------------------------------------------------------------
__global__ __launch_bounds__(128) void leaf_softmax_kernel(const float* __restrict__ pi) {
    const int row = blockIdx.x * 4 + (threadIdx.x >> 5);
    const int lane = threadIdx.x & 31;
    const float* pr = pi + (size_t)row * C_;

    float v[4];
#pragma unroll
    for (int j = 0; j < 4; j++) {
        int c = lane + j * 32;
        v[j] = (c < C_) ? pr[c] : -1e30f;
    }
    float m = fmaxf(fmaxf(v[0], v[1]), fmaxf(v[2], v[3]));
#pragma unroll
    for (int o = 16; o; o >>= 1) m = fmaxf(m, __shfl_xor_sync(0xffffffffu, m, o));

    float e[4];
    float s = 0.0f;
#pragma unroll
    for (int j = 0; j < 4; j++) {
        int c = lane + j * 32;
        e[j] = (c < C_) ? __expf(v[j] - m) : 0.0f;
        s += e[j];
    }
#pragma unroll
    for (int o = 16; o; o >>= 1) s += __shfl_xor_sync(0xffffffffu, s, o);
    float inv = 1.0f / s;
#pragma unroll
    for (int j = 0; j < 4; j++) {
        int c = lane + j * 32;
        if (c < C_) g_leafp[(size_t)row * C_ + c] = e[j] * inv;
    }
}

// ---------------------------------------------------------------------------
// mu[t,b,l] = prod_{d=0..8} route(p[t,b,node(d,l)], side(d,l))
// ---------------------------------------------------------------------------
__global__ __launch_bounds__(128) void mu_kernel() {
    __shared__ float sp[L_];
    const size_t tb = blockIdx.x;
    const float* pr = g_p + tb * L_;
    const int tid = threadIdx.x;
#pragma unroll
    for (int i = 0; i < 4; i++) sp[tid + i * 128] = pr[tid + i * 128];
    __syncthreads();
#pragma unroll
    for (int i = 0; i < 4; i++) {
        int l = tid + i * 128;
        float prod = 1.0f;
#pragma unroll
        for (int d = 0; d <= 8; d++) {
            int node = (1 << d) - 1 + (l >> (9 - d));
            float v = sp[node];
            prod *= ((l >> (8 - d)) & 1) ? (1.0f - v) : v;
        }
        g_mu[tb * L_ + l] = prod;
    }
}

// ---------------------------------------------------------------------------
// Deterministic reduction over k-splits + final log
// ---------------------------------------------------------------------------
__global__ __launch_bounds__(256) void reduce_log_kernel(float* __restrict__ out) {
    const int i = blockIdx.x * 256 + threadIdx.x;
    float s = 0.0f;
#pragma unroll
    for (int ks = 0; ks < KSPLIT; ks++) s += g_part[(size_t)ks * B_ * C_ + i];
    out[i] = logf(s * (1.0f / (float)(L_ * T_)));
}

extern "C" void kernel_launch(void* const* d_in, const int* in_sizes, int n_in,
                              void* d_out, int out_size) {
    const float* feat = (const float*)d_in[0];
    const float* W1 = (const float*)d_in[1];
    const float* b1 = (const float*)d_in[2];
    const float* W2 = (const float*)d_in[3];
    const float* b2 = (const float*)d_in[4];
    const float* pi = (const float*)d_in[5];
    float* out = (float*)d_out;

    // Leaf softmax first (independent of the GEMM chain)
    leaf_softmax_kernel<<<(T_ * L_) / 4, 128>>>(pi);
    // Stage 1: h = relu(feat @ W1 + b1)
    gemm_tf32<0, F_DIM, H_><<<dim3(B_ / 128, 1, T_), 256>>>(feat, W1, b1);
    // Stage 2: p = sigmoid(h @ W2 + b2)
    gemm_tf32<1, H_, L_><<<dim3(B_ / 128, L_ / 128, T_), 256>>>(nullptr, W2, b2);
    // Routing products
    mu_kernel<<<T_ * B_, 128>>>();
    // Final contraction: one tree per k-split (deterministic partials)
    gemm_tf32<2, L_, C_><<<dim3(B_ / 128, KSPLIT), 256>>>(nullptr, nullptr, nullptr);
    // Reduce + log
    reduce_log_kernel<<<(B_ * C_) / 256, 256>>>(out);
}

// round 3
// speedup vs baseline: 2.8111x; 1.3042x over previous
#include <cuda_runtime.h>
#include <cuda_bf16.h>
#include <cuda_fp16.h>
#include <math.h>

#define T_ 16
#define B_ 1024
#define F_DIM 512
#define H_ 128
#define L_ 512
#define C_ 100
#define KSPLIT 16

// Scratch (static device globals -- no allocation allowed)
__device__ __nv_bfloat16 g_h[(size_t)T_ * B_ * H_];       // 4 MB
__device__ __nv_bfloat16 g_mu[(size_t)T_ * B_ * L_];      // 16 MB
__device__ __nv_bfloat16 g_leafp[(size_t)T_ * L_ * C_];   // 1.6 MB
__device__ float g_part[(size_t)KSPLIT * B_ * C_];        // 6.5 MB

__device__ __forceinline__ unsigned pkf(float lo, float hi) {
    __nv_bfloat162 h = __floats2bfloat162_rn(lo, hi);
    return *reinterpret_cast<unsigned*>(&h);
}

__device__ __forceinline__ void mma_bf16(float* d, const unsigned* a, const unsigned* b) {
    asm volatile(
        "mma.sync.aligned.m16n8k16.row.col.f32.bf16.bf16.f32 "
        "{%0,%1,%2,%3}, {%4,%5,%6,%7}, {%8,%9}, {%0,%1,%2,%3};\n"
        : "+f"(d[0]), "+f"(d[1]), "+f"(d[2]), "+f"(d[3])
        : "r"(a[0]), "r"(a[1]), "r"(a[2]), "r"(a[3]), "r"(b[0]), "r"(b[1]));
}

// ---------------------------------------------------------------------------
// Stage 1: h = relu(feat @ W1 + b1), bf16 mma, out bf16.
// 128x128 tile, BK=32, 256 threads. grid (B/128, 1, T)
// ---------------------------------------------------------------------------
__global__ __launch_bounds__(256) void gemm1_bf16(const float* __restrict__ feat,
                                                  const float* __restrict__ W1,
                                                  const float* __restrict__ b1) {
    __shared__ unsigned As[128][20];   // bf16x2 pairs over k (16 kp + pad 4)
    __shared__ unsigned Bs[16][132];   // [kp][n], pad 4

    const int tid = threadIdx.x;
    const int wid = tid >> 5, lane = tid & 31;
    const int warp_m = wid >> 2, warp_n = wid & 3;
    const int lq = lane >> 2, lr = lane & 3;
    const int t = blockIdx.z;
    const int b0 = blockIdx.x * 128;

    const float* Wb = W1 + (size_t)t * F_DIM * H_;
    const float* bb = b1 + (size_t)t * H_;

    float acc[4][4][4];
#pragma unroll
    for (int i = 0; i < 4; i++)
#pragma unroll
        for (int j = 0; j < 4; j++)
#pragma unroll
            for (int q = 0; q < 4; q++) acc[i][j][q] = 0.0f;

    for (int k0 = 0; k0 < F_DIM; k0 += 32) {
        // A: 128x32 fp32 -> bf16 pairs (k contiguous). 1024 float4 tasks.
#pragma unroll
        for (int i = 0; i < 4; i++) {
            int e = tid + i * 256;
            int r = e >> 3, c4 = e & 7;
            float4 v = *reinterpret_cast<const float4*>(&feat[(size_t)(b0 + r) * F_DIM + k0 + c4 * 4]);
            As[r][c4 * 2] = pkf(v.x, v.y);
            As[r][c4 * 2 + 1] = pkf(v.z, v.w);
        }
        // B: pairs over k (strided rows). 512 tasks (kp, n4).
#pragma unroll
        for (int i = 0; i < 2; i++) {
            int e = tid + i * 256;
            int kp = e >> 5, n4 = e & 31;
            const float* r0 = Wb + (size_t)(k0 + 2 * kp) * H_ + n4 * 4;
            float4 x = *reinterpret_cast<const float4*>(r0);
            float4 y = *reinterpret_cast<const float4*>(r0 + H_);
            Bs[kp][n4 * 4 + 0] = pkf(x.x, y.x);
            Bs[kp][n4 * 4 + 1] = pkf(x.y, y.y);
            Bs[kp][n4 * 4 + 2] = pkf(x.z, y.z);
            Bs[kp][n4 * 4 + 3] = pkf(x.w, y.w);
        }
        __syncthreads();

#pragma unroll
        for (int kt = 0; kt < 2; kt++) {
            const int kb = kt * 8;
            unsigned afr[4][4], bfr[4][2];
#pragma unroll
            for (int im = 0; im < 4; im++) {
                int r = warp_m * 64 + im * 16;
                afr[im][0] = As[r + lq][kb + lr];
                afr[im][1] = As[r + 8 + lq][kb + lr];
                afr[im][2] = As[r + lq][kb + 4 + lr];
                afr[im][3] = As[r + 8 + lq][kb + 4 + lr];
            }
#pragma unroll
            for (int jn = 0; jn < 4; jn++) {
                int c = warp_n * 32 + jn * 8 + lq;
                bfr[jn][0] = Bs[kb + lr][c];
                bfr[jn][1] = Bs[kb + 4 + lr][c];
            }
#pragma unroll
            for (int im = 0; im < 4; im++)
#pragma unroll
                for (int jn = 0; jn < 4; jn++) mma_bf16(acc[im][jn], afr[im], bfr[jn]);
        }
        __syncthreads();
    }

    unsigned* gh = reinterpret_cast<unsigned*>(g_h);
#pragma unroll
    for (int im = 0; im < 4; im++) {
#pragma unroll
        for (int half = 0; half < 2; half++) {
            int r = warp_m * 64 + im * 16 + half * 8 + lq;
#pragma unroll
            for (int jn = 0; jn < 4; jn++) {
                int c = warp_n * 32 + jn * 8 + lr * 2;
                float x0 = fmaxf(acc[im][jn][half * 2 + 0] + bb[c], 0.0f);
                float x1 = fmaxf(acc[im][jn][half * 2 + 1] + bb[c + 1], 0.0f);
                gh[((size_t)t * B_ + b0 + r) * (H_ / 2) + (c >> 1)] = pkf(x0, x1);
            }
        }
    }
}

// ---------------------------------------------------------------------------
// Stage 2 fused: p = sigmoid(h @ W2 + b2) staged in fp16 smem, then
// mu[t,b,l] routing products via tree-doubling, written bf16.
// One CTA: 128 b-rows x full L=512. grid (B/128, T), 256 threads, dyn smem.
// ---------------------------------------------------------------------------
#define SM2_HA (128 * 68)
#define SM2_BS (16 * 132)
#define SM2_BYTES ((SM2_HA + SM2_BS) * 4 + 128 * 520 * 2)

__global__ __launch_bounds__(256, 1) void stage2_fused(const float* __restrict__ W2,
                                                       const float* __restrict__ b2) {
    extern __shared__ unsigned smemu[];
    unsigned* hA = smemu;                              // [128][68]
    unsigned* Bs = smemu + SM2_HA;                     // [16][132]
    __half* ph = reinterpret_cast<__half*>(smemu + SM2_HA + SM2_BS);  // [128][520]

    const int tid = threadIdx.x;
    const int wid = tid >> 5, lane = tid & 31;
    const int warp_m = wid >> 2, warp_n = wid & 3;
    const int lq = lane >> 2, lr = lane & 3;
    const int t = blockIdx.y;
    const int b0 = blockIdx.x * 128;

    // Load h tile (128 x 128 bf16 = 128 x 64 u32), resident for all chunks.
    const unsigned* hsrc = reinterpret_cast<const unsigned*>(g_h) + ((size_t)t * B_ + b0) * (H_ / 2);
#pragma unroll
    for (int i = 0; i < 8; i++) {
        int e = tid + i * 256;
        int r = e >> 4, q = e & 15;
        uint4 v = *reinterpret_cast<const uint4*>(&hsrc[(size_t)r * 64 + q * 4]);
        *reinterpret_cast<uint4*>(&hA[r * 68 + q * 4]) = v;
    }
    __syncthreads();

    const float* W2t = W2 + (size_t)t * H_ * L_;
    const float* bbt = b2 + (size_t)t * L_;

#pragma unroll 1
    for (int chunk = 0; chunk < 4; chunk++) {
        const int n0c = chunk * 128;
        float acc[4][4][4];
#pragma unroll
        for (int i = 0; i < 4; i++)
#pragma unroll
            for (int j = 0; j < 4; j++)
#pragma unroll
                for (int q = 0; q < 4; q++) acc[i][j][q] = 0.0f;

#pragma unroll 1
        for (int k0s = 0; k0s < 4; k0s++) {
            const int k0 = k0s * 32;
            // B tile: W2 rows k0..k0+31, cols n0c..n0c+127, bf16 pairs over k.
#pragma unroll
            for (int i = 0; i < 2; i++) {
                int e = tid + i * 256;
                int kp = e >> 5, n4 = e & 31;
                const float* r0 = W2t + (size_t)(k0 + 2 * kp) * L_ + n0c + n4 * 4;
                float4 x = *reinterpret_cast<const float4*>(r0);
                float4 y = *reinterpret_cast<const float4*>(r0 + L_);
                Bs[kp * 132 + n4 * 4 + 0] = pkf(x.x, y.x);
                Bs[kp * 132 + n4 * 4 + 1] = pkf(x.y, y.y);
                Bs[kp * 132 + n4 * 4 + 2] = pkf(x.z, y.z);
                Bs[kp * 132 + n4 * 4 + 3] = pkf(x.w, y.w);
            }
            __syncthreads();
#pragma unroll
            for (int kt = 0; kt < 2; kt++) {
                const int kbG = k0s * 16 + kt * 8;  // hA pair base (global k)
                const int kbB = kt * 8;             // Bs pair base
                unsigned afr[4][4], bfr[4][2];
#pragma unroll
                for (int im = 0; im < 4; im++) {
                    int r = warp_m * 64 + im * 16;
                    afr[im][0] = hA[(r + lq) * 68 + kbG + lr];
                    afr[im][1] = hA[(r + 8 + lq) * 68 + kbG + lr];
                    afr[im][2] = hA[(r + lq) * 68 + kbG + 4 + lr];
                    afr[im][3] = hA[(r + 8 + lq) * 68 + kbG + 4 + lr];
                }
#pragma unroll
                for (int jn = 0; jn < 4; jn++) {
                    int c = warp_n * 32 + jn * 8 + lq;
                    bfr[jn][0] = Bs[(kbB + lr) * 132 + c];
                    bfr[jn][1] = Bs[(kbB + 4 + lr) * 132 + c];
                }
#pragma unroll
                for (int im = 0; im < 4; im++)
#pragma unroll
                    for (int jn = 0; jn < 4; jn++) mma_bf16(acc[im][jn], afr[im], bfr[jn]);
            }
            __syncthreads();
        }

        // Epilogue: sigmoid -> ph (fp16)
#pragma unroll
        for (int im = 0; im < 4; im++) {
#pragma unroll
            for (int half = 0; half < 2; half++) {
                int r = warp_m * 64 + im * 16 + half * 8 + lq;
#pragma unroll
                for (int jn = 0; jn < 4; jn++) {
                    int c = warp_n * 32 + jn * 8 + lr * 2;
                    float x0 = 1.0f / (1.0f + __expf(-(acc[im][jn][half * 2 + 0] + bbt[n0c + c])));
                    float x1 = 1.0f / (1.0f + __expf(-(acc[im][jn][half * 2 + 1] + bbt[n0c + c + 1])));
                    *reinterpret_cast<__half2*>(&ph[r * 520 + n0c + c]) = __floats2half2_rn(x0, x1);
                }
            }
        }
    }
    __syncthreads();

    // mu phase: each thread handles 8 (row, 32-leaf block) tasks via tree-doubling.
    unsigned* muout = reinterpret_cast<unsigned*>(g_mu) + ((size_t)t * B_ + b0) * (L_ / 2);
#pragma unroll 1
    for (int i = 0; i < 8; i++) {
        int task = i * 256 + tid;
        int row = task >> 4;
        int l0 = (task & 15) << 5;
        const __half* sp = ph + row * 520;

        float pref = 1.0f;
#pragma unroll
        for (int d = 0; d < 4; d++) {
            int node = (1 << d) - 1 + (l0 >> (9 - d));
            float v = __half2float(sp[node]);
            pref *= ((l0 >> (8 - d)) & 1) ? (1.0f - v) : v;
        }

        float cur[32];
        cur[0] = pref;
#pragma unroll
        for (int d = 4; d <= 8; d++) {
            const int width = 1 << (d - 4);
            const int nbase = (1 << d) - 1 + (l0 >> (9 - d));
#pragma unroll
            for (int ii = width - 1; ii >= 0; ii--) {
                float v = __half2float(sp[nbase + ii]);
                float x = cur[ii];
                cur[2 * ii] = x * v;
                cur[2 * ii + 1] = x * (1.0f - v);
            }
        }

        unsigned w[16];
#pragma unroll
        for (int j = 0; j < 16; j++) w[j] = pkf(cur[2 * j], cur[2 * j + 1]);
        unsigned* dst = muout + (size_t)row * (L_ / 2) + (l0 >> 1);
#pragma unroll
        for (int j4 = 0; j4 < 4; j4++)
            *reinterpret_cast<uint4*>(dst + j4 * 4) =
                *reinterpret_cast<uint4*>(&w[j4 * 4]);
    }
}

// ---------------------------------------------------------------------------
// Leaf softmax: leafp[t,l,:] = softmax(pi[t,l,:]) -> bf16. One warp per row.
// ---------------------------------------------------------------------------
__global__ __launch_bounds__(128) void leaf_softmax_kernel(const float* __restrict__ pi) {
    const int row = blockIdx.x * 4 + (threadIdx.x >> 5);
    const int lane = threadIdx.x & 31;
    const float* pr = pi + (size_t)row * C_;

    float v[4];
#pragma unroll
    for (int j = 0; j < 4; j++) {
        int c = lane + j * 32;
        v[j] = (c < C_) ? pr[c] : -1e30f;
    }
    float m = fmaxf(fmaxf(v[0], v[1]), fmaxf(v[2], v[3]));
#pragma unroll
    for (int o = 16; o; o >>= 1) m = fmaxf(m, __shfl_xor_sync(0xffffffffu, m, o));

    float e[4];
    float s = 0.0f;
#pragma unroll
    for (int j = 0; j < 4; j++) {
        int c = lane + j * 32;
        e[j] = (c < C_) ? __expf(v[j] - m) : 0.0f;
        s += e[j];
    }
#pragma unroll
    for (int o = 16; o; o >>= 1) s += __shfl_xor_sync(0xffffffffu, s, o);
    float inv = 1.0f / s;
#pragma unroll
    for (int j = 0; j < 4; j++) {
        int c = lane + j * 32;
        if (c < C_) g_leafp[(size_t)row * C_ + c] = __float2bfloat16(e[j] * inv);
    }
}

// ---------------------------------------------------------------------------
// Final contraction: part[t] = mu[t] @ leafp[t], one tree per y-block.
// 128x128 tile (100 valid cols), BK=32, bf16 mma. grid (B/128, T)
// ---------------------------------------------------------------------------
__global__ __launch_bounds__(256) void final_bf16() {
    __shared__ unsigned As[128][20];
    __shared__ unsigned Bs[16][132];

    const int tid = threadIdx.x;
    const int wid = tid >> 5, lane = tid & 31;
    const int warp_m = wid >> 2, warp_n = wid & 3;
    const int lq = lane >> 2, lr = lane & 3;
    const int t = blockIdx.y;
    const int b0 = blockIdx.x * 128;

    const unsigned* mu_u = reinterpret_cast<const unsigned*>(g_mu) + ((size_t)t * B_ + b0) * (L_ / 2);
    const __nv_bfloat16* lp = g_leafp + (size_t)t * L_ * C_;

    float acc[4][4][4];
#pragma unroll
    for (int i = 0; i < 4; i++)
#pragma unroll
        for (int j = 0; j < 4; j++)
#pragma unroll
            for (int q = 0; q < 4; q++) acc[i][j][q] = 0.0f;

    for (int k0 = 0; k0 < L_; k0 += 32) {
        // A: mu pairs contiguous over k. 512 uint4 tasks.
#pragma unroll
        for (int i = 0; i < 2; i++) {
            int e = tid + i * 256;
            int r = e >> 2, q = e & 3;
            uint4 v = *reinterpret_cast<const uint4*>(&mu_u[(size_t)r * (L_ / 2) + (k0 >> 1) + q * 4]);
            *reinterpret_cast<uint4*>(&As[r][q * 4]) = v;
        }
        // B: leafp pairs over k (strided rows), zero-pad col >= 100.
#pragma unroll
        for (int i = 0; i < 8; i++) {
            int e = tid + i * 256;
            int kp = e >> 7, col = e & 127;
            unsigned val = 0;
            if (col < C_) {
                unsigned short lo = *reinterpret_cast<const unsigned short*>(&lp[(size_t)(k0 + 2 * kp) * C_ + col]);
                unsigned short hi = *reinterpret_cast<const unsigned short*>(&lp[(size_t)(k0 + 2 * kp + 1) * C_ + col]);
                val = (unsigned)lo | ((unsigned)hi << 16);
            }
            Bs[kp][col] = val;
        }
        __syncthreads();

#pragma unroll
        for (int kt = 0; kt < 2; kt++) {
            const int kb = kt * 8;
            unsigned afr[4][4], bfr[4][2];
#pragma unroll
            for (int im = 0; im < 4; im++) {
                int r = warp_m * 64 + im * 16;
                afr[im][0] = As[r + lq][kb + lr];
                afr[im][1] = As[r + 8 + lq][kb + lr];
                afr[im][2] = As[r + lq][kb + 4 + lr];
                afr[im][3] = As[r + 8 + lq][kb + 4 + lr];
            }
#pragma unroll
            for (int jn = 0; jn < 4; jn++) {
                int c = warp_n * 32 + jn * 8 + lq;
                bfr[jn][0] = Bs[kb + lr][c];
                bfr[jn][1] = Bs[kb + 4 + lr][c];
            }
#pragma unroll
            for (int im = 0; im < 4; im++)
#pragma unroll
                for (int jn = 0; jn < 4; jn++) mma_bf16(acc[im][jn], afr[im], bfr[jn]);
        }
        __syncthreads();
    }

    float* pb = g_part + (size_t)t * B_ * C_;
#pragma unroll
    for (int im = 0; im < 4; im++) {
#pragma unroll
        for (int half = 0; half < 2; half++) {
            int r = warp_m * 64 + im * 16 + half * 8 + lq;
#pragma unroll
            for (int jn = 0; jn < 4; jn++) {
                int c = warp_n * 32 + jn * 8 + lr * 2;
                if (c >= C_) continue;
                *reinterpret_cast<float2*>(&pb[(size_t)(b0 + r) * C_ + c]) =
                    make_float2(acc[im][jn][half * 2 + 0], acc[im][jn][half * 2 + 1]);
            }
        }
    }
}

// ---------------------------------------------------------------------------
// Deterministic reduction over trees + final log
// ---------------------------------------------------------------------------
__global__ __launch_bounds__(256) void reduce_log_kernel(float* __restrict__ out) {
    const int i = blockIdx.x * 256 + threadIdx.x;
    float s = 0.0f;
#pragma unroll
    for (int ks = 0; ks < KSPLIT; ks++) s += g_part[(size_t)ks * B_ * C_ + i];
    out[i] = logf(s * (1.0f / (float)(L_ * T_)));
}

extern "C" void kernel_launch(void* const* d_in, const int* in_sizes, int n_in,
                              void* d_out, int out_size) {
    const float* feat = (const float*)d_in[0];
    const float* W1 = (const float*)d_in[1];
    const float* b1 = (const float*)d_in[2];
    const float* W2 = (const float*)d_in[3];
    const float* b2 = (const float*)d_in[4];
    const float* pi = (const float*)d_in[5];
    float* out = (float*)d_out;

    cudaFuncSetAttribute(stage2_fused, cudaFuncAttributeMaxDynamicSharedMemorySize, SM2_BYTES);

    leaf_softmax_kernel<<<(T_ * L_) / 4, 128>>>(pi);
    gemm1_bf16<<<dim3(B_ / 128, 1, T_), 256>>>(feat, W1, b1);
    stage2_fused<<<dim3(B_ / 128, T_), 256, SM2_BYTES>>>(W2, b2);
    final_bf16<<<dim3(B_ / 128, T_), 256>>>();
    reduce_log_kernel<<<(B_ * C_) / 256, 256>>>(out);
}